// round 16
// baseline (speedup 1.0000x reference)
#include <cuda_runtime.h>
#include <cuda_fp16.h>
#include <cstdint>

// ============================================================================
// QuadraticConv2D via fp16 HMMA GEMM, register-carried pipeline (depth 3),
// SPLIT-K x2: grid = 392 tiles x 2 K-halves (27 pairs each; 27 = 9 triples).
//   - output zero-initialized (graph memset node), halves combine via
//     atomicAdd f32 (exactly 2 deterministic contributions per element)
//   - p=0 folded into fp32 bias, added by K-half 0 only
//   - per-CTA schedule identical to the 150us baseline (triple-buffered SMEM,
//     wait_group 1, 2M x 4N warp grid, unrolled buffer triples)
// out[m,o] = bias[o] + sum_{p=(i,j)>0} sum_c S_i[m,c]*S_j[m,c]*W[p,c,o]
// ============================================================================

#define HW     56
#define CH     64
#define OD     128
#define NPOS   (8 * 56 * 56)      // 25088
#define MT     64                 // M rows per CTA
#define NTILES (NPOS / MT)        // 392
#define BDIM   256
#define NPAIRS 55
#define KSPLIT 2
#define NHALF  27                 // GEMM pairs per K-half (1..27 / 28..54)

#define ASTR   144                // A row stride bytes
#define BSTR   272                // B row stride bytes

// SMEM layout (bytes), triple buffered
#define ABUF_SZ   9216            // 64 x 144
#define A_OFF(b)  ((b) * ABUF_SZ)                 // b in 0..2
#define BBUF_SZ   17408           // 64 x 272
#define B_OFF(b)  (27648 + (b) * BBUF_SZ)
#define MB_OFF    79872
#define MK_OFF    80128
#define SMEM_TOTAL 80384

// pre-converted weights [p][c*136 + o] fp16, and fp32 bias from pair 0
__device__ __align__(16) __half g_Bh[NPAIRS][CH * (BSTR / 2)];
__device__ __align__(16) float  g_bias[OD];

__constant__ unsigned char cII[55] = {
    0,0,0,0,0,0,0,0,0,0, 1,1,1,1,1,1,1,1,1, 2,2,2,2,2,2,2,2,
    3,3,3,3,3,3,3, 4,4,4,4,4,4, 5,5,5,5,5, 6,6,6,6, 7,7,7, 8,8, 9};
__constant__ unsigned char cJJ[55] = {
    0,1,2,3,4,5,6,7,8,9, 1,2,3,4,5,6,7,8,9, 2,3,4,5,6,7,8,9,
    3,4,5,6,7,8,9, 4,5,6,7,8,9, 5,6,7,8,9, 6,7,8,9, 7,8,9, 8,9, 9};

__device__ __forceinline__ uint32_t smem_to_u32(const void* p) {
    uint32_t a;
    asm("{ .reg .u64 t; cvta.to.shared.u64 t, %1; cvt.u32.u64 %0, t; }"
        : "=r"(a) : "l"(p));
    return a;
}

#define LDSM_X4(r, addr) \
    asm volatile("ldmatrix.sync.aligned.m8n8.x4.shared.b16 {%0,%1,%2,%3}, [%4];" \
                 : "=r"((r)[0]), "=r"((r)[1]), "=r"((r)[2]), "=r"((r)[3]) \
                 : "r"(addr))
#define LDSM_X4T(r, addr) \
    asm volatile("ldmatrix.sync.aligned.m8n8.x4.trans.shared.b16 {%0,%1,%2,%3}, [%4];" \
                 : "=r"((r)[0]), "=r"((r)[1]), "=r"((r)[2]), "=r"((r)[3]) \
                 : "r"(addr))
#define CP_ASYNC16(dst, src) \
    asm volatile("cp.async.cg.shared.global [%0], [%1], 16;" \
                 :: "r"(dst), "l"(src) : "memory")
#define CP_COMMIT() asm volatile("cp.async.commit_group;" ::: "memory")
#define CP_WAIT1()  asm volatile("cp.async.wait_group 1;" ::: "memory")

__device__ __forceinline__ void mma_f16(float* c, const uint32_t* a, const uint32_t* b) {
    asm volatile(
        "mma.sync.aligned.m16n8k16.row.col.f32.f16.f16.f32 "
        "{%0,%1,%2,%3}, {%4,%5,%6,%7}, {%8,%9}, {%0,%1,%2,%3};"
        : "+f"(c[0]), "+f"(c[1]), "+f"(c[2]), "+f"(c[3])
        : "r"(a[0]), "r"(a[1]), "r"(a[2]), "r"(a[3]), "r"(b[0]), "r"(b[1]));
}

// ---------------------------------------------------------------------------
// Prep (single kernel, vectorized): weight convert + pair-0 bias reduction
// ---------------------------------------------------------------------------
__global__ void prep_all(const float* __restrict__ wt) {
    int idx = blockIdx.x * blockDim.x + threadIdx.x;       // over 55*64*32 float4s
    if (idx < NPAIRS * CH * (OD / 4)) {
        int p = idx / (CH * (OD / 4));
        int r = idx - p * (CH * (OD / 4));
        int c = r / (OD / 4);
        int o4 = (r - c * (OD / 4)) * 4;
        float4 w = *(const float4*)(wt + (size_t)(p * CH + c) * OD + o4);
        __half2 h0 = __floats2half2_rn(w.x, w.y);
        __half2 h1 = __floats2half2_rn(w.z, w.w);
        *(uint2*)&g_Bh[p][c * (BSTR / 2) + o4] =
            make_uint2(*(unsigned*)&h0, *(unsigned*)&h1);
    }
    if (blockIdx.x == 0 && threadIdx.x < OD) {
        int o = threadIdx.x;
        float s = 0.f;
        #pragma unroll
        for (int c = 0; c < CH; c++) s += wt[c * OD + o];   // pair 0 slice
        g_bias[o] = s;
    }
}

// ---------------------------------------------------------------------------
__global__ void __launch_bounds__(BDIM, 2)
qconv_pipe(const float* __restrict__ in, float* __restrict__ out) {
    extern __shared__ unsigned char smem[];
    const uint32_t sb = smem_to_u32(smem);
    int* mbase_s = (int*)(smem + MB_OFF);
    int* mmask_s = (int*)(smem + MK_OFF);

    const int tid  = threadIdx.x;
    const int wid  = tid >> 5;
    const int lane = tid & 31;
    const int tile = blockIdx.x >> 1;
    const int half = blockIdx.x & 1;
    const int gm0  = tile * MT;
    const int P0   = 1 + half * NHALF;          // first GEMM pair of this half

    if (tid < MT) {
        int gm  = gm0 + tid;
        int b   = gm / (HW * HW);
        int rem = gm - b * HW * HW;
        int h   = rem / HW;
        int w   = rem - h * HW;
        mbase_s[tid] = ((b * HW + (h - 1)) * HW + (w - 1)) * CH;
        int mask = 0;
        #pragma unroll
        for (int kk = 0; kk < 9; kk++) {
            int hh = h + kk / 3 - 1, ww = w + kk % 3 - 1;
            if (hh >= 0 && hh < HW && ww >= 0 && ww < HW) mask |= (1 << kk);
        }
        mmask_s[tid] = mask;
    }
    __syncthreads();

    // A-gen mapping: thread owns row am, 16-channel quarter cq
    const int am   = tid >> 2;
    const int cq   = (tid & 3) * 16;
    const int base = mbase_s[am];
    const int mask = mmask_s[am];

    // GEMM mapping: 8 warps = 2(M) x 4(N); warp tile 32 x 32
    const int m0 = (wid & 1) * 32;
    const int n0 = (wid >> 1) * 32;
    const uint32_t aoff = (uint32_t)((m0 + (lane & 15)) * ASTR + (lane >> 4) * 16);
    const uint32_t boff = (uint32_t)((lane & 15) * BSTR + (n0 + ((lane >> 4) & 1) * 8) * 2);

    float acc[2][4][4];
    #pragma unroll
    for (int mt = 0; mt < 2; mt++)
        #pragma unroll
        for (int nt = 0; nt < 4; nt++)
            #pragma unroll
            for (int q = 0; q < 4; q++) acc[mt][nt][q] = 0.f;

    const float4 ONES = make_float4(1.f, 1.f, 1.f, 1.f);
    const float4 ZERO = make_float4(0.f, 0.f, 0.f, 0.f);

    // ---- helpers ----
    auto issue_loads = [&](int p, float4* si4, float4* sj4) {
        const int i = cII[p], j = cJJ[p];
        const int kj = j - 1, ki = i - 1;
        const int offj = ((kj / 3) * HW + (kj % 3)) * CH;          // j >= 1 here
        const int offi = (i > 0) ? ((ki / 3) * HW + (ki % 3)) * CH : 0;
        const bool vj = (mask >> kj) & 1;
        const bool vi = (i == 0) || ((mask >> ki) & 1);
        #pragma unroll
        for (int g = 0; g < 4; g++) {
            const int c = cq + g * 4;
            sj4[g] = vj ? *(const float4*)(in + base + offj + c) : ZERO;
            si4[g] = (i == 0) ? ONES : (vi ? *(const float4*)(in + base + offi + c) : ZERO);
        }
    };
    auto store_A = [&](uint32_t a_off_bytes, const float4* si4, const float4* sj4) {
        unsigned char* ah = smem + a_off_bytes;
        #pragma unroll
        for (int g = 0; g < 4; g++) {
            const int c = cq + g * 4;
            __half2 hA = __floats2half2_rn(si4[g].x * sj4[g].x, si4[g].y * sj4[g].y);
            __half2 hB = __floats2half2_rn(si4[g].z * sj4[g].z, si4[g].w * sj4[g].w);
            *(uint2*)(ah + am * ASTR + c * 2) =
                make_uint2(*(unsigned*)&hA, *(unsigned*)&hB);
        }
    };
    auto stage_B = [&](int p, uint32_t b_off_bytes) {
        const char* shp = (const char*)g_Bh[p];
        const uint32_t dh = sb + b_off_bytes;
        // 1088 16B chunks = 4*256 + 64
        #pragma unroll
        for (int t = 0; t < 4; t++) {
            const int x = tid + t * BDIM;
            CP_ASYNC16(dh + x * 16, shp + x * 16);
        }
        if (tid < 64) {
            const int x = 1024 + tid;
            CP_ASYNC16(dh + x * 16, shp + x * 16);
        }
    };
    auto mma_pair = [&](uint32_t a_off_bytes, uint32_t b_off_bytes) {
        const uint32_t abase = sb + a_off_bytes + aoff;
        const uint32_t bbase = sb + b_off_bytes + boff;
        #pragma unroll
        for (int kk = 0; kk < 4; kk++) {
            uint32_t a0[4], a1[4];
            LDSM_X4(a0, abase + kk * 32);
            LDSM_X4(a1, abase + kk * 32 + 16 * ASTR);
            const uint32_t bb = bbase + kk * 16 * BSTR;
            #pragma unroll
            for (int t = 0; t < 4; t += 2) {
                uint32_t bh[4];
                LDSM_X4T(bh, bb + t * 16);
                mma_f16(acc[0][t],     a0, bh);
                mma_f16(acc[0][t + 1], a0, bh + 2);
                mma_f16(acc[1][t],     a1, bh);
                mma_f16(acc[1][t + 1], a1, bh + 2);
            }
        }
    };

    // One pipeline step; BUF/NXT are compile-time constants at each call site.
    #define STEP(BUF, NXT, PP, MORE) do {                                      \
        float4 si4[4], sj4[4];                                                 \
        if (MORE) issue_loads((PP) + 2, si4, sj4);  /* LDGs fly across MMA */  \
        CP_WAIT1();                    /* B(PP) landed (this thread) */        \
        __syncthreads();               /* B/A(PP) visible; bufs free */        \
        if (MORE) stage_B((PP) + 2, B_OFF(NXT));                               \
        CP_COMMIT();                   /* unconditional: group invariant */    \
        mma_pair(A_OFF(BUF), B_OFF(BUF));           /* 32 HMMA per warp */     \
        if (MORE) store_A(A_OFF(NXT), si4, sj4);    /* regs -> SMEM */         \
    } while (0)

    // ---- prologue: first two pairs of this half ----
    stage_B(P0,     B_OFF(0)); CP_COMMIT();      // group 0
    stage_B(P0 + 1, B_OFF(1)); CP_COMMIT();      // group 1
    {
        float4 si4[4], sj4[4];
        issue_loads(P0,     si4, sj4); store_A(A_OFF(0), si4, sj4);
        issue_loads(P0 + 1, si4, sj4); store_A(A_OFF(1), si4, sj4);
    }

    // ---- main loop: 27 steps = 8 full triples + tail triple ----
    int p = P0;
    #pragma unroll 1
    for (int t3 = 0; t3 < 8; t3++) {
        STEP(0, 2, p,     true);
        STEP(1, 0, p + 1, true);
        STEP(2, 1, p + 2, true);
        p += 3;
    }
    STEP(0, 2, p,     true);    // stages pair P0+26
    STEP(1, 0, p + 1, false);
    STEP(2, 1, p + 2, false);
    #undef STEP

    // ---- epilogue: atomicAdd into zeroed output; bias from K-half 0 ----
    float* op = out + (size_t)gm0 * OD;
    const int rr = lane >> 2;
    const int cc = (lane & 3) * 2;
    #pragma unroll
    for (int mt = 0; mt < 2; mt++) {
        #pragma unroll
        for (int nt = 0; nt < 4; nt++) {
            const int r0 = m0 + mt * 16 + rr;
            const int cn = n0 + nt * 8 + cc;
            const float b0 = (half == 0) ? g_bias[cn]     : 0.f;
            const float b1 = (half == 0) ? g_bias[cn + 1] : 0.f;
            atomicAdd(op + (size_t)r0 * OD + cn,           acc[mt][nt][0] + b0);
            atomicAdd(op + (size_t)r0 * OD + cn + 1,       acc[mt][nt][1] + b1);
            atomicAdd(op + (size_t)(r0 + 8) * OD + cn,     acc[mt][nt][2] + b0);
            atomicAdd(op + (size_t)(r0 + 8) * OD + cn + 1, acc[mt][nt][3] + b1);
        }
    }
}

// ---------------------------------------------------------------------------
extern "C" void kernel_launch(void* const* d_in, const int* in_sizes, int n_in,
                              void* d_out, int out_size) {
    const float* in = (const float*)d_in[0];
    const float* wt = (const float*)d_in[1];
    if (n_in >= 2 && in_sizes[0] == NPAIRS * CH * OD) {
        const float* t = in; in = wt; wt = t;
    }
    float* out = (float*)d_out;

    prep_all<<<(NPAIRS * CH * (OD / 4) + 255) / 256, 256>>>(wt);
    cudaMemsetAsync(out, 0, (size_t)out_size * sizeof(float));

    cudaFuncSetAttribute(qconv_pipe,
                         cudaFuncAttributeMaxDynamicSharedMemorySize, SMEM_TOTAL);
    qconv_pipe<<<NTILES * KSPLIT, BDIM, SMEM_TOTAL>>>(in, out);
}